// round 12
// baseline (speedup 1.0000x reference)
#include <cuda_runtime.h>
#include <cuda_bf16.h>
#include <mma.h>
#include <cstdint>

using namespace nvcuda;

#define NN 10000
#define EE 640000
#define CC 128
#define HH 512
#define OO 128
#define MPAD 10112   // 79*128 = 158*64
#define CAP 192      // per-row neighbor bucket capacity

// ---------------- static scratch ----------------
__device__ int   g_cursor[NN];
__device__ int   g_bucket[NN * CAP];
// bf16 hi/lo operand planes (pad rows of hcat stay zero: never written)
__device__ __align__(16) __nv_bfloat16 g_hcat_hi[MPAD * 256];
__device__ __align__(16) __nv_bfloat16 g_hcat_lo[MPAD * 256];
__device__ __align__(16) __nv_bfloat16 g_w1_hi[256 * 512];   // [K=256, N=512]
__device__ __align__(16) __nv_bfloat16 g_w1_lo[256 * 512];
__device__ __align__(16) __nv_bfloat16 g_hmid_hi[MPAD * 512];
__device__ __align__(16) __nv_bfloat16 g_hmid_lo[MPAD * 512];
__device__ __align__(16) __nv_bfloat16 g_w2_hi[512 * 128];   // [K=512, N=128]
__device__ __align__(16) __nv_bfloat16 g_w2_lo[512 * 128];

// ---------------- helpers ----------------
__device__ __forceinline__ void split_bf16(float v, __nv_bfloat16& hi, __nv_bfloat16& lo) {
    hi = __float2bfloat16(v);
    lo = __float2bfloat16(v - __bfloat162float(hi));
}

__device__ __forceinline__ void split_store4(float4 v,
                                             __nv_bfloat16* hi, __nv_bfloat16* lo) {
    __nv_bfloat16 h0, h1, h2, h3, l0, l1, l2, l3;
    split_bf16(v.x, h0, l0); split_bf16(v.y, h1, l1);
    split_bf16(v.z, h2, l2); split_bf16(v.w, h3, l3);
    uint2 hp, lp;
    hp.x = (uint32_t)__bfloat16_as_ushort(h0) | ((uint32_t)__bfloat16_as_ushort(h1) << 16);
    hp.y = (uint32_t)__bfloat16_as_ushort(h2) | ((uint32_t)__bfloat16_as_ushort(h3) << 16);
    lp.x = (uint32_t)__bfloat16_as_ushort(l0) | ((uint32_t)__bfloat16_as_ushort(l1) << 16);
    lp.y = (uint32_t)__bfloat16_as_ushort(l2) | ((uint32_t)__bfloat16_as_ushort(l3) << 16);
    *reinterpret_cast<uint2*>(hi) = hp;
    *reinterpret_cast<uint2*>(lo) = lp;
}

__device__ __forceinline__ uint32_t smem_u32(const void* p) {
    return (uint32_t)__cvta_generic_to_shared(p);
}
__device__ __forceinline__ void cp16(uint32_t dst, const void* src) {
    asm volatile("cp.async.ca.shared.global [%0], [%1], 16;" :: "r"(dst), "l"(src));
}
#define CP_COMMIT() asm volatile("cp.async.commit_group;" ::: "memory")
#define CP_WAIT1()  asm volatile("cp.async.wait_group 1;" ::: "memory")
#define CP_WAIT0()  asm volatile("cp.async.wait_group 0;" ::: "memory")

// ---------------- bucket build ----------------
__global__ void k_zero() {
    int i = blockIdx.x * blockDim.x + threadIdx.x;
    if (i < NN) g_cursor[i] = 0;
}

__global__ void k_fill(const int* __restrict__ ei) {
    int e = blockIdx.x * blockDim.x + threadIdx.x;
    if (e < EE) {
        int r = ei[e];
        int c = ei[EE + e];
        int pos = atomicAdd(&g_cursor[r], 1);
        if (pos < CAP) g_bucket[r * CAP + pos] = c;
    }
}

// ---------------- weight split (no transpose: [K,N] stays n-contiguous) ----------------
__global__ void k_prep(const float* __restrict__ w, __nv_bfloat16* __restrict__ hi,
                       __nv_bfloat16* __restrict__ lo, int n4) {
    int i = blockIdx.x * blockDim.x + threadIdx.x;
    if (i >= n4) return;
    float4 v = *reinterpret_cast<const float4*>(&w[i * 4]);
    split_store4(v, hi + i * 4, lo + i * 4);
}

// ---------------- aggregation: one warp per row -> split bf16 planes ----------------
__global__ void k_agg(const float* __restrict__ x) {
    int gw   = (blockIdx.x * blockDim.x + threadIdx.x) >> 5;
    int lane = threadIdx.x & 31;
    if (gw >= NN) return;
    const float4* x4 = reinterpret_cast<const float4*>(x);

    float4 xv = x4[gw * 32 + lane];

    float ax = 0.f, ay = 0.f, az = 0.f, aw = 0.f;
    int cnt = min(g_cursor[gw], CAP);
    const int* bk = &g_bucket[gw * CAP];
    int i = 0;
    for (; i + 4 <= cnt; i += 4) {
        int i0 = bk[i + 0];
        int i1 = bk[i + 1];
        int i2 = bk[i + 2];
        int i3 = bk[i + 3];
        float4 v0 = x4[i0 * 32 + lane];
        float4 v1 = x4[i1 * 32 + lane];
        float4 v2 = x4[i2 * 32 + lane];
        float4 v3 = x4[i3 * 32 + lane];
        ax += (v0.x + v1.x) + (v2.x + v3.x);
        ay += (v0.y + v1.y) + (v2.y + v3.y);
        az += (v0.z + v1.z) + (v2.z + v3.z);
        aw += (v0.w + v1.w) + (v2.w + v3.w);
    }
    for (; i < cnt; i++) {
        int id = bk[i];
        float4 v = x4[id * 32 + lane];
        ax += v.x; ay += v.y; az += v.z; aw += v.w;
    }
    float inv = 1.0f / (float)max(cnt, 1);
    float4 m = make_float4(ax * inv, ay * inv, az * inv, aw * inv);

    int base = gw * 256 + lane * 4;
    split_store4(xv, g_hcat_hi + base, g_hcat_lo + base);
    split_store4(m,  g_hcat_hi + base + 128, g_hcat_lo + base + 128);
}

// ---------------- cp.async double-buffered WMMA split GEMM ----------------
// C = relu?((Ahi+Alo)(Bhi+Blo) + bias): AhBh + AhBl + AlBh.
// A*: [MPAD,K] bf16 rm. B*: [K,Nn] bf16 rm. CTA BM x 128, BK=16, 2 stages.
// 8 warps (2 M x 4 N), warp tile (BM/2) x 32.

#define ASTR2 24    // A smem k-row stride (elems; 48B rows)
#define BSTR2 136   // B smem n-row stride (elems; 272B rows)
#define ESTR 36     // epilogue fp32 stride (144B, 16B-aligned)

template <int BM, bool RELU, bool SPLIT_OUT>
__global__ void __launch_bounds__(256, 2) k_pgemm(
    const __nv_bfloat16* __restrict__ Ahi, const __nv_bfloat16* __restrict__ Alo,
    const __nv_bfloat16* __restrict__ Bhi, const __nv_bfloat16* __restrict__ Blo,
    const float* __restrict__ bias,
    float* __restrict__ OutF, __nv_bfloat16* __restrict__ Ohi, __nv_bfloat16* __restrict__ Olo,
    int Nn, int K, int Mstore)
{
    constexpr int I   = BM / 32;             // warp M-subtiles
    constexpr int SA  = BM * ASTR2;          // one A plane (elems)
    constexpr int SB  = 16 * BSTR2;          // one B plane (elems)
    constexpr int STG = 2 * SA + 2 * SB;     // one stage (elems)
    constexpr int SM_GEMM = 2 * STG * 2;     // bytes
    constexpr int SM_EPI  = 8 * 16 * ESTR * 4;
    constexpr int SM_SZ   = SM_GEMM > SM_EPI ? SM_GEMM : SM_EPI;
    __shared__ __align__(16) char sm[SM_SZ];
    __nv_bfloat16* smb = reinterpret_cast<__nv_bfloat16*>(sm);
    float* ebuf = reinterpret_cast<float*>(sm);

    int t    = threadIdx.x;
    int wid  = t >> 5;
    int lane = t & 31;
    int wm   = wid & 1;
    int wn   = wid >> 1;
    int bm   = blockIdx.x * BM;
    int bn   = blockIdx.y * 128;

    wmma::fragment<wmma::accumulator, 16, 16, 16, float> acc[I][2];
    #pragma unroll
    for (int i = 0; i < I; i++)
        #pragma unroll
        for (int j = 0; j < 2; j++)
            wmma::fill_fragment(acc[i][j], 0.0f);

    // stage loader: BK=16 chunk kc -> stage s
    auto load_stage = [&](int kc, int s) {
        int kofs = kc * 16;
        __nv_bfloat16* st = smb + s * STG;
        uint32_t a_hi = smem_u32(st);
        uint32_t a_lo = smem_u32(st + SA);
        uint32_t b_hi = smem_u32(st + 2 * SA);
        uint32_t b_lo = smem_u32(st + 2 * SA + SB);
        // A: BM rows x 16 cols, 2 segs/row per plane
        #pragma unroll
        for (int s0 = t; s0 < BM * 2; s0 += 256) {
            int row = s0 >> 1, seg = s0 & 1;
            size_t gofs = (size_t)(bm + row) * K + kofs + seg * 8;
            uint32_t sofs = (uint32_t)(row * ASTR2 + seg * 8) * 2;
            cp16(a_hi + sofs, Ahi + gofs);
            cp16(a_lo + sofs, Alo + gofs);
        }
        // B: 16 k-rows x 128 cols, 16 segs/row per plane
        {
            int row = t >> 4, seg = t & 15;
            size_t gofs = (size_t)(kofs + row) * Nn + bn + seg * 8;
            uint32_t sofs = (uint32_t)(row * BSTR2 + seg * 8) * 2;
            cp16(b_hi + sofs, Bhi + gofs);
            cp16(b_lo + sofs, Blo + gofs);
        }
    };

    int nch = K >> 4;
    load_stage(0, 0);
    CP_COMMIT();

    #pragma unroll 1
    for (int kc = 0; kc < nch; kc++) {
        if (kc + 1 < nch) load_stage(kc + 1, (kc + 1) & 1);
        CP_COMMIT();
        CP_WAIT1();
        __syncthreads();

        __nv_bfloat16* st = smb + (kc & 1) * STG;
        __nv_bfloat16* As_hi = st;
        __nv_bfloat16* As_lo = st + SA;
        __nv_bfloat16* Bs_hi = st + 2 * SA;
        __nv_bfloat16* Bs_lo = st + 2 * SA + SB;

        wmma::fragment<wmma::matrix_b, 16, 16, 16, __nv_bfloat16, wmma::row_major> bh[2], bl[2];
        #pragma unroll
        for (int j = 0; j < 2; j++) {
            wmma::load_matrix_sync(bh[j], &Bs_hi[wn * 32 + j * 16], BSTR2);
            wmma::load_matrix_sync(bl[j], &Bs_lo[wn * 32 + j * 16], BSTR2);
        }
        #pragma unroll
        for (int i = 0; i < I; i++) {
            wmma::fragment<wmma::matrix_a, 16, 16, 16, __nv_bfloat16, wmma::row_major> ah, al;
            int aofs = (wm * (BM / 2) + i * 16) * ASTR2;
            wmma::load_matrix_sync(ah, &As_hi[aofs], ASTR2);
            wmma::load_matrix_sync(al, &As_lo[aofs], ASTR2);
            #pragma unroll
            for (int j = 0; j < 2; j++) {
                wmma::mma_sync(acc[i][j], ah, bh[j], acc[i][j]);
                wmma::mma_sync(acc[i][j], ah, bl[j], acc[i][j]);
                wmma::mma_sync(acc[i][j], al, bh[j], acc[i][j]);
            }
        }
        __syncthreads();
    }
    CP_WAIT0();
    __syncthreads();

    // ---- epilogue: per-warp smem stage, bias(+relu), fp32 or split-bf16 out ----
    int chalf = lane & 1;
    int erow  = lane >> 1;
    float4 bvals[4];
    #pragma unroll
    for (int q = 0; q < 4; q++)
        bvals[q] = *reinterpret_cast<const float4*>(&bias[bn + wn * 32 + chalf * 16 + q * 4]);

    float* wbuf = ebuf + wid * (16 * ESTR);
    #pragma unroll
    for (int i = 0; i < I; i++) {
        wmma::store_matrix_sync(wbuf +  0, acc[i][0], ESTR, wmma::mem_row_major);
        wmma::store_matrix_sync(wbuf + 16, acc[i][1], ESTR, wmma::mem_row_major);
        __syncwarp();
        int grow = bm + wm * (BM / 2) + i * 16 + erow;
        if (grow < Mstore) {
            #pragma unroll
            for (int q = 0; q < 4; q++) {
                float4 v = *reinterpret_cast<const float4*>(
                    &wbuf[erow * ESTR + chalf * 16 + q * 4]);
                v.x += bvals[q].x; v.y += bvals[q].y;
                v.z += bvals[q].z; v.w += bvals[q].w;
                if (RELU) {
                    v.x = fmaxf(v.x, 0.f); v.y = fmaxf(v.y, 0.f);
                    v.z = fmaxf(v.z, 0.f); v.w = fmaxf(v.w, 0.f);
                }
                size_t gofs = (size_t)grow * Nn + bn + wn * 32 + chalf * 16 + q * 4;
                if (SPLIT_OUT) {
                    split_store4(v, Ohi + gofs, Olo + gofs);
                } else {
                    *reinterpret_cast<float4*>(&OutF[gofs]) = v;
                }
            }
        }
        __syncwarp();
    }
}

extern "C" void kernel_launch(void* const* d_in, const int* in_sizes, int n_in,
                              void* d_out, int out_size)
{
    const float* x  = (const float*)d_in[0];
    const int*   ei = (const int*)d_in[1];    // [2,E] int32
    const float* w1 = (const float*)d_in[2];  // [256,512]
    const float* b1 = (const float*)d_in[3];  // [512]
    const float* w2 = (const float*)d_in[4];  // [512,128]
    const float* b2 = (const float*)d_in[5];  // [128]
    float* out = (float*)d_out;               // [N,128]

    __nv_bfloat16 *hcat_hi, *hcat_lo, *w1_hi, *w1_lo, *hmid_hi, *hmid_lo, *w2_hi, *w2_lo;
    cudaGetSymbolAddress((void**)&hcat_hi, g_hcat_hi);
    cudaGetSymbolAddress((void**)&hcat_lo, g_hcat_lo);
    cudaGetSymbolAddress((void**)&w1_hi, g_w1_hi);
    cudaGetSymbolAddress((void**)&w1_lo, g_w1_lo);
    cudaGetSymbolAddress((void**)&hmid_hi, g_hmid_hi);
    cudaGetSymbolAddress((void**)&hmid_lo, g_hmid_lo);
    cudaGetSymbolAddress((void**)&w2_hi, g_w2_hi);
    cudaGetSymbolAddress((void**)&w2_lo, g_w2_lo);

    k_zero<<<(NN + 255) / 256, 256>>>();
    k_fill<<<(EE + 255) / 256, 256>>>(ei);
    k_prep<<<(256 * 512 / 4 + 255) / 256, 256>>>(w1, w1_hi, w1_lo, 256 * 512 / 4);
    k_prep<<<(512 * 128 / 4 + 255) / 256, 256>>>(w2, w2_hi, w2_lo, 512 * 128 / 4);
    k_agg<<<(NN * 32 + 255) / 256, 256>>>(x);

    // GEMM1: hcat[MPAD,256] @ w1[256,512] -> hmid planes (bias+relu+split)
    dim3 g1(MPAD / 128, 512 / 128);   // 79 x 4
    k_pgemm<128, true, true><<<g1, 256>>>(hcat_hi, hcat_lo, w1_hi, w1_lo, b1,
                                          nullptr, hmid_hi, hmid_lo, 512, 256, MPAD);

    // GEMM2: hmid[MPAD,512] @ w2[512,128] -> out fp32 (bias), rows < NN
    dim3 g2(MPAD / 64, 1);            // 158 x 1
    k_pgemm<64, false, false><<<g2, 256>>>(hmid_hi, hmid_lo, w2_hi, w2_lo, b2,
                                           out, nullptr, nullptr, 128, 512, NN);
}

// round 14
// speedup vs baseline: 1.0910x; 1.0910x over previous
#include <cuda_runtime.h>
#include <cuda_bf16.h>
#include <mma.h>
#include <cstdint>

using namespace nvcuda;

#define NN 10000
#define EE 640000
#define CC 128
#define HH 512
#define OO 128
#define MPAD 10112   // 79*128 = 158*64
#define CAP 192      // per-row neighbor bucket capacity

// ---------------- static scratch ----------------
__device__ int   g_cursor[NN];
__device__ int   g_bucket[NN * CAP];
// bf16 hi/lo operand planes (pad rows of hcat stay zero: never written)
__device__ __align__(16) __nv_bfloat16 g_hcat_hi[MPAD * 256];
__device__ __align__(16) __nv_bfloat16 g_hcat_lo[MPAD * 256];
__device__ __align__(16) __nv_bfloat16 g_w1_hi[256 * 512];   // [K=256, N=512]
__device__ __align__(16) __nv_bfloat16 g_w1_lo[256 * 512];
__device__ __align__(16) __nv_bfloat16 g_hmid_hi[MPAD * 512];
__device__ __align__(16) __nv_bfloat16 g_hmid_lo[MPAD * 512];
__device__ __align__(16) __nv_bfloat16 g_w2_hi[512 * 128];   // [K=512, N=128]
__device__ __align__(16) __nv_bfloat16 g_w2_lo[512 * 128];

// ---------------- helpers ----------------
__device__ __forceinline__ void split_bf16(float v, __nv_bfloat16& hi, __nv_bfloat16& lo) {
    hi = __float2bfloat16(v);
    lo = __float2bfloat16(v - __bfloat162float(hi));
}

__device__ __forceinline__ void split_store4(float4 v,
                                             __nv_bfloat16* hi, __nv_bfloat16* lo) {
    __nv_bfloat16 h0, h1, h2, h3, l0, l1, l2, l3;
    split_bf16(v.x, h0, l0); split_bf16(v.y, h1, l1);
    split_bf16(v.z, h2, l2); split_bf16(v.w, h3, l3);
    uint2 hp, lp;
    hp.x = (uint32_t)__bfloat16_as_ushort(h0) | ((uint32_t)__bfloat16_as_ushort(h1) << 16);
    hp.y = (uint32_t)__bfloat16_as_ushort(h2) | ((uint32_t)__bfloat16_as_ushort(h3) << 16);
    lp.x = (uint32_t)__bfloat16_as_ushort(l0) | ((uint32_t)__bfloat16_as_ushort(l1) << 16);
    lp.y = (uint32_t)__bfloat16_as_ushort(l2) | ((uint32_t)__bfloat16_as_ushort(l3) << 16);
    *reinterpret_cast<uint2*>(hi) = hp;
    *reinterpret_cast<uint2*>(lo) = lp;
}

__device__ __forceinline__ uint32_t smem_u32(const void* p) {
    return (uint32_t)__cvta_generic_to_shared(p);
}
__device__ __forceinline__ void cp16(uint32_t dst, const void* src) {
    asm volatile("cp.async.ca.shared.global [%0], [%1], 16;" :: "r"(dst), "l"(src));
}
#define CP_COMMIT() asm volatile("cp.async.commit_group;" ::: "memory")
#define CP_WAIT0()  asm volatile("cp.async.wait_group 0;" ::: "memory")

// ---------------- bucket build ----------------
__global__ void k_zero() {
    int i = blockIdx.x * blockDim.x + threadIdx.x;
    if (i < NN) g_cursor[i] = 0;
}

__global__ void k_fill(const int* __restrict__ ei) {
    int e = blockIdx.x * blockDim.x + threadIdx.x;
    if (e < EE) {
        int r = ei[e];
        int c = ei[EE + e];
        int pos = atomicAdd(&g_cursor[r], 1);
        if (pos < CAP) g_bucket[r * CAP + pos] = c;
    }
}

// ---------------- merged weight split (one launch) ----------------
#define W1Q (256 * 512 / 4)
#define W2Q (512 * 128 / 4)
__global__ void k_prep(const float* __restrict__ w1, const float* __restrict__ w2) {
    int i = blockIdx.x * blockDim.x + threadIdx.x;
    if (i < W1Q) {
        float4 v = *reinterpret_cast<const float4*>(&w1[i * 4]);
        split_store4(v, g_w1_hi + i * 4, g_w1_lo + i * 4);
    } else if (i < W1Q + W2Q) {
        int j = i - W1Q;
        float4 v = *reinterpret_cast<const float4*>(&w2[j * 4]);
        split_store4(v, g_w2_hi + j * 4, g_w2_lo + j * 4);
    }
}

// ---------------- aggregation: one warp per row -> split bf16 planes ----------------
__global__ void k_agg(const float* __restrict__ x) {
    int gw   = (blockIdx.x * blockDim.x + threadIdx.x) >> 5;
    int lane = threadIdx.x & 31;
    if (gw >= NN) return;
    const float4* x4 = reinterpret_cast<const float4*>(x);

    float4 xv = x4[gw * 32 + lane];

    float ax = 0.f, ay = 0.f, az = 0.f, aw = 0.f;
    int cnt = min(g_cursor[gw], CAP);
    const int* bk = &g_bucket[gw * CAP];
    int i = 0;
    for (; i + 4 <= cnt; i += 4) {
        int i0 = bk[i + 0];
        int i1 = bk[i + 1];
        int i2 = bk[i + 2];
        int i3 = bk[i + 3];
        float4 v0 = x4[i0 * 32 + lane];
        float4 v1 = x4[i1 * 32 + lane];
        float4 v2 = x4[i2 * 32 + lane];
        float4 v3 = x4[i3 * 32 + lane];
        ax += (v0.x + v1.x) + (v2.x + v3.x);
        ay += (v0.y + v1.y) + (v2.y + v3.y);
        az += (v0.z + v1.z) + (v2.z + v3.z);
        aw += (v0.w + v1.w) + (v2.w + v3.w);
    }
    for (; i < cnt; i++) {
        int id = bk[i];
        float4 v = x4[id * 32 + lane];
        ax += v.x; ay += v.y; az += v.z; aw += v.w;
    }
    float inv = 1.0f / (float)max(cnt, 1);
    float4 m = make_float4(ax * inv, ay * inv, az * inv, aw * inv);

    int base = gw * 256 + lane * 4;
    split_store4(xv, g_hcat_hi + base, g_hcat_lo + base);
    split_store4(m,  g_hcat_hi + base + 128, g_hcat_lo + base + 128);
}

// ---------------- pre-split WMMA GEMM: BK=32, single buffer, cp.async ----------------
// C = relu?((Ahi+Alo)(Bhi+Blo) + bias): AhBh + AhBl + AlBh.
// A*: [MPAD,K] bf16 rm. B*: [K,Nn] bf16 rm. CTA BM x 128, 8 warps (2M x 4N),
// warp tile (BM/2) x 32. 2 CTAs/SM.

#define ASTR2 40    // A smem m-row stride (elems; 80B)
#define BSTR2 136   // B smem k-row stride (elems; 272B)
#define ESTR 36     // epilogue fp32 stride (144B, 16B-aligned)

template <int BM, bool RELU, bool SPLIT_OUT>
__global__ void __launch_bounds__(256, 2) k_pgemm(
    const __nv_bfloat16* __restrict__ Ahi, const __nv_bfloat16* __restrict__ Alo,
    const __nv_bfloat16* __restrict__ Bhi, const __nv_bfloat16* __restrict__ Blo,
    const float* __restrict__ bias,
    float* __restrict__ OutF, __nv_bfloat16* __restrict__ Ohi, __nv_bfloat16* __restrict__ Olo,
    int Nn, int K, int Mstore)
{
    constexpr int I   = BM / 32;             // warp M-subtiles
    constexpr int SA  = BM * ASTR2;          // one A plane (elems)
    constexpr int SB  = 32 * BSTR2;          // one B plane (elems)
    constexpr int SM_GEMM = (2 * SA + 2 * SB) * 2;   // bytes
    constexpr int SM_EPI  = 8 * 16 * ESTR * 4;
    constexpr int SM_SZ   = SM_GEMM > SM_EPI ? SM_GEMM : SM_EPI;
    __shared__ __align__(16) char sm[SM_SZ];
    __nv_bfloat16* As_hi = reinterpret_cast<__nv_bfloat16*>(sm);
    __nv_bfloat16* As_lo = As_hi + SA;
    __nv_bfloat16* Bs_hi = As_lo + SA;
    __nv_bfloat16* Bs_lo = Bs_hi + SB;
    float* ebuf = reinterpret_cast<float*>(sm);

    int t    = threadIdx.x;
    int wid  = t >> 5;
    int lane = t & 31;
    int wm   = wid & 1;
    int wn   = wid >> 1;
    int bm   = blockIdx.x * BM;
    int bn   = blockIdx.y * 128;

    uint32_t a_hi = smem_u32(As_hi);
    uint32_t a_lo = smem_u32(As_lo);
    uint32_t b_hi = smem_u32(Bs_hi);
    uint32_t b_lo = smem_u32(Bs_lo);

    wmma::fragment<wmma::accumulator, 16, 16, 16, float> acc[I][2];
    #pragma unroll
    for (int i = 0; i < I; i++)
        #pragma unroll
        for (int j = 0; j < 2; j++)
            wmma::fill_fragment(acc[i][j], 0.0f);

    int nch = K >> 5;
    #pragma unroll 1
    for (int kc = 0; kc < nch; kc++) {
        int kofs = kc * 32;
        // ---- A: BM rows x 32 cols bf16, 4 segs/row per plane ----
        #pragma unroll
        for (int s0 = t; s0 < BM * 4; s0 += 256) {
            int row = s0 >> 2, seg = s0 & 3;
            size_t gofs = (size_t)(bm + row) * K + kofs + seg * 8;
            uint32_t sofs = (uint32_t)(row * ASTR2 + seg * 8) * 2;
            cp16(a_hi + sofs, Ahi + gofs);
            cp16(a_lo + sofs, Alo + gofs);
        }
        // ---- B: 32 k-rows x 128 cols bf16, 16 segs/row per plane ----
        #pragma unroll
        for (int it = 0; it < 2; it++) {
            int s0 = t + it * 256;
            int row = s0 >> 4, seg = s0 & 15;
            size_t gofs = (size_t)(kofs + row) * Nn + bn + seg * 8;
            uint32_t sofs = (uint32_t)(row * BSTR2 + seg * 8) * 2;
            cp16(b_hi + sofs, Bhi + gofs);
            cp16(b_lo + sofs, Blo + gofs);
        }
        CP_COMMIT();
        CP_WAIT0();
        __syncthreads();

        #pragma unroll
        for (int ks = 0; ks < 2; ks++) {
            wmma::fragment<wmma::matrix_b, 16, 16, 16, __nv_bfloat16, wmma::row_major> bh[2], bl[2];
            #pragma unroll
            for (int j = 0; j < 2; j++) {
                wmma::load_matrix_sync(bh[j], &Bs_hi[(ks * 16) * BSTR2 + wn * 32 + j * 16], BSTR2);
                wmma::load_matrix_sync(bl[j], &Bs_lo[(ks * 16) * BSTR2 + wn * 32 + j * 16], BSTR2);
            }
            #pragma unroll
            for (int i = 0; i < I; i++) {
                wmma::fragment<wmma::matrix_a, 16, 16, 16, __nv_bfloat16, wmma::row_major> ah, al;
                int aofs = (wm * (BM / 2) + i * 16) * ASTR2 + ks * 16;
                wmma::load_matrix_sync(ah, &As_hi[aofs], ASTR2);
                wmma::load_matrix_sync(al, &As_lo[aofs], ASTR2);
                #pragma unroll
                for (int j = 0; j < 2; j++) {
                    wmma::mma_sync(acc[i][j], ah, bh[j], acc[i][j]);
                    wmma::mma_sync(acc[i][j], ah, bl[j], acc[i][j]);
                    wmma::mma_sync(acc[i][j], al, bh[j], acc[i][j]);
                }
            }
        }
        __syncthreads();
    }

    // ---- epilogue: per-warp smem stage, bias(+relu), fp32 or split-bf16 out ----
    int chalf = lane & 1;
    int erow  = lane >> 1;
    float4 bvals[4];
    #pragma unroll
    for (int q = 0; q < 4; q++)
        bvals[q] = *reinterpret_cast<const float4*>(&bias[bn + wn * 32 + chalf * 16 + q * 4]);

    float* wbuf = ebuf + wid * (16 * ESTR);
    #pragma unroll
    for (int i = 0; i < I; i++) {
        wmma::store_matrix_sync(wbuf +  0, acc[i][0], ESTR, wmma::mem_row_major);
        wmma::store_matrix_sync(wbuf + 16, acc[i][1], ESTR, wmma::mem_row_major);
        __syncwarp();
        int grow = bm + wm * (BM / 2) + i * 16 + erow;
        if (grow < Mstore) {
            #pragma unroll
            for (int q = 0; q < 4; q++) {
                float4 v = *reinterpret_cast<const float4*>(
                    &wbuf[erow * ESTR + chalf * 16 + q * 4]);
                v.x += bvals[q].x; v.y += bvals[q].y;
                v.z += bvals[q].z; v.w += bvals[q].w;
                if (RELU) {
                    v.x = fmaxf(v.x, 0.f); v.y = fmaxf(v.y, 0.f);
                    v.z = fmaxf(v.z, 0.f); v.w = fmaxf(v.w, 0.f);
                }
                size_t gofs = (size_t)grow * Nn + bn + wn * 32 + chalf * 16 + q * 4;
                if (SPLIT_OUT) {
                    split_store4(v, Ohi + gofs, Olo + gofs);
                } else {
                    *reinterpret_cast<float4*>(&OutF[gofs]) = v;
                }
            }
        }
        __syncwarp();
    }
}

extern "C" void kernel_launch(void* const* d_in, const int* in_sizes, int n_in,
                              void* d_out, int out_size)
{
    const float* x  = (const float*)d_in[0];
    const int*   ei = (const int*)d_in[1];    // [2,E] int32
    const float* w1 = (const float*)d_in[2];  // [256,512]
    const float* b1 = (const float*)d_in[3];  // [512]
    const float* w2 = (const float*)d_in[4];  // [512,128]
    const float* b2 = (const float*)d_in[5];  // [128]
    float* out = (float*)d_out;               // [N,128]

    __nv_bfloat16 *hcat_hi, *hcat_lo, *w1_hi, *w1_lo, *hmid_hi, *hmid_lo, *w2_hi, *w2_lo;
    cudaGetSymbolAddress((void**)&hcat_hi, g_hcat_hi);
    cudaGetSymbolAddress((void**)&hcat_lo, g_hcat_lo);
    cudaGetSymbolAddress((void**)&w1_hi, g_w1_hi);
    cudaGetSymbolAddress((void**)&w1_lo, g_w1_lo);
    cudaGetSymbolAddress((void**)&hmid_hi, g_hmid_hi);
    cudaGetSymbolAddress((void**)&hmid_lo, g_hmid_lo);
    cudaGetSymbolAddress((void**)&w2_hi, g_w2_hi);
    cudaGetSymbolAddress((void**)&w2_lo, g_w2_lo);

    k_zero<<<(NN + 255) / 256, 256>>>();
    k_fill<<<(EE + 255) / 256, 256>>>(ei);
    k_prep<<<(W1Q + W2Q + 255) / 256, 256>>>(w1, w2);
    k_agg<<<(NN * 32 + 255) / 256, 256>>>(x);

    // GEMM1: hcat[MPAD,256] @ w1[256,512] -> hmid planes (bias+relu+split)
    dim3 g1(MPAD / 128, 512 / 128);   // 79 x 4
    k_pgemm<128, true, true><<<g1, 256>>>(hcat_hi, hcat_lo, w1_hi, w1_lo, b1,
                                          nullptr, hmid_hi, hmid_lo, 512, 256, MPAD);

    // GEMM2: hmid[MPAD,512] @ w2[512,128] -> out fp32 (bias), rows < NN
    dim3 g2(MPAD / 64, 1);            // 158 x 1
    k_pgemm<64, false, false><<<g2, 256>>>(hmid_hi, hmid_lo, w2_hi, w2_lo, b2,
                                           out, nullptr, nullptr, 128, 512, NN);
}